// round 1
// baseline (speedup 1.0000x reference)
#include <cuda_runtime.h>

// Problem constants
constexpr int NU = 4096;
constexpr int NS = 8192;
constexpr int ND = 32;
constexpr int NREG = 128;
#define GA_CONST 0.1f

// Main-kernel tiling
constexpr int TSB = 256;   // items per block
constexpr int TUB = 64;    // users per block

// ---------------- device scratch (no allocations allowed) ----------------
__device__ double g_acc;                 // final scalar accumulator (loss + GA*region)
__device__ float  g_rsum[NREG * ND];     // per-region embedding sums
__device__ float  g_rcnt[NREG];          // per-region counts

// ---------------- packed f32x2 helpers (sm_100+ FFMA2) ----------------
static __device__ __forceinline__ void ffma2(unsigned long long &d,
                                             unsigned long long a,
                                             unsigned long long b) {
    asm("fma.rn.f32x2 %0, %1, %2, %3;" : "=l"(d) : "l"(a), "l"(b), "l"(d));
}
static __device__ __forceinline__ float2 unpack2(unsigned long long v) {
    float2 r;
    asm("mov.b64 {%0, %1}, %2;" : "=f"(r.x), "=f"(r.y) : "l"(v));
    return r;
}

// ---------------- small kernels: zero / region segment-sum / region loss ----------------
__global__ void k_zero() {
    int t = threadIdx.x;
    for (int i = t; i < NREG * ND; i += blockDim.x) g_rsum[i] = 0.0f;
    if (t < NREG) g_rcnt[t] = 0.0f;
    if (t == 0) g_acc = 0.0;
}

__global__ void k_region_sum(const float* __restrict__ user_emb,
                             const int* __restrict__ region_index) {
    int u    = (blockIdx.x * blockDim.x + threadIdx.x) >> 5;  // warp per user
    int lane = threadIdx.x & 31;
    if (u >= NU) return;
    int r = region_index[u];
    atomicAdd(&g_rsum[r * ND + lane], user_emb[u * ND + lane]);
    if (lane == 0) atomicAdd(&g_rcnt[r], 1.0f);
}

__global__ void k_region_loss(const float* __restrict__ user_emb,
                              const int* __restrict__ region_index) {
    int u    = (blockIdx.x * blockDim.x + threadIdx.x) >> 5;  // warp per user
    int lane = threadIdx.x & 31;
    if (u >= NU) return;
    int r = region_index[u];
    float cnt = g_rcnt[r];
    float e   = user_emb[u * ND + lane];
    float loo = (g_rsum[r * ND + lane] - e) / fmaxf(cnt - 1.0f, 1.0f);
    float dev = fabsf(e - loo);
#pragma unroll
    for (int o = 16; o; o >>= 1) dev += __shfl_xor_sync(0xffffffffu, dev, o);
    if (lane == 0 && cnt > 1.0f) atomicAdd(&g_acc, (double)(GA_CONST * dev));
}

// ---------------- main fused kernel ----------------
// Block tile: TUB(64) users x TSB(256) items. 8 warps:
//   strip = (warp&3)*64 items (each lane owns 2 consecutive items -> item frags in regs)
//   uhalf = (warp>>2)*32 users (inner loop, user vecs broadcast from smem)
// Streaming loads (mask/true_qos/weight) are coalesced float2/int2 along s.
__global__ __launch_bounds__(256, 2) void k_main(const float* __restrict__ user_emb,
                                                 const float* __restrict__ item_emb,
                                                 const int*   __restrict__ mask,
                                                 const float* __restrict__ tq,
                                                 const float* __restrict__ wgt) {
    __shared__ float s_item[TSB * 34];   // padded stride 34 floats (8B-aligned rows)
    __shared__ float s_user[TUB * ND];
    __shared__ float s_red[8];

    const int tid   = threadIdx.x;
    const int sbase = blockIdx.x * TSB;
    const int ubase0 = blockIdx.y * TUB;

    // Stage item tile: items [sbase, sbase+256) are a contiguous 8192-float chunk
    {
        const float4* g = (const float4*)(item_emb + (size_t)sbase * ND);
#pragma unroll
        for (int i = 0; i < (TSB * ND) / (256 * 4); ++i) {  // 8 iters
            int idx = tid + i * 256;          // float4 index
            float4 v = g[idx];
            int f = idx * 4;
            int row = f >> 5, col = f & 31;
            float* p = s_item + row * 34 + col;
            p[0] = v.x; p[1] = v.y; p[2] = v.z; p[3] = v.w;
        }
    }
    // Stage user tile: contiguous 2048 floats
    {
        const float4* g = (const float4*)(user_emb + (size_t)ubase0 * ND);
        float4* sm = (float4*)s_user;
#pragma unroll
        for (int i = 0; i < (TUB * ND) / (256 * 4); ++i)  // 2 iters
            sm[tid + i * 256] = g[tid + i * 256];
    }
    __syncthreads();

    const int warp = tid >> 5, lane = tid & 31;
    const int strip = (warp & 3) * 64;
    const int uhalf = (warp >> 2) * 32;
    const int i0 = strip + 2 * lane;          // even -> 8B aligned rows

    // Item fragments: 2 item vectors (32 floats each) as 16 packed f32x2 each
    unsigned long long a0[16], a1[16];
    {
        const unsigned long long* r0 = (const unsigned long long*)(s_item + i0 * 34);
        const unsigned long long* r1 = (const unsigned long long*)(s_item + (i0 + 1) * 34);
#pragma unroll
        for (int d = 0; d < 16; ++d) { a0[d] = r0[d]; a1[d] = r1[d]; }
    }

    const int scol = sbase + i0;
    const long base = (long)(ubase0 + uhalf) * NS + scol;
    const float* suv = s_user + uhalf * ND;

    float lsum = 0.0f;
#pragma unroll 4
    for (int u = 0; u < 32; ++u) {
        const long off = base + (long)u * NS;
        const int2   m2 = __ldcs((const int2*)(mask + off));
        const float2 t2 = __ldcs((const float2*)(tq + off));
        const float2 w2 = __ldcs((const float2*)(wgt + off));

        unsigned long long acc0 = 0ull, acc1 = 0ull;
        const ulonglong2* uv = (const ulonglong2*)(suv + u * ND);  // uniform broadcast
#pragma unroll
        for (int k = 0; k < 8; ++k) {
            ulonglong2 up = uv[k];               // LDS.128, lane-uniform
            ffma2(acc0, a0[2 * k],     up.x);
            ffma2(acc0, a0[2 * k + 1], up.y);
            ffma2(acc1, a1[2 * k],     up.x);
            ffma2(acc1, a1[2 * k + 1], up.y);
        }
        float2 s0 = unpack2(acc0), s1 = unpack2(acc1);
        float dot0 = s0.x + s0.y;
        float dot1 = s1.x + s1.y;
        float p0 = m2.x ? dot0 : 0.0f;
        float p1 = m2.y ? dot1 : 0.0f;
        float d0 = p0 - t2.x;
        float d1 = p1 - t2.y;
        lsum = fmaf(w2.x * d0, d0, lsum);
        lsum = fmaf(w2.y * d1, d1, lsum);
    }

    // Reduce: warp shfl -> smem -> one double atomic per block
#pragma unroll
    for (int o = 16; o; o >>= 1) lsum += __shfl_xor_sync(0xffffffffu, lsum, o);
    if (lane == 0) s_red[warp] = lsum;
    __syncthreads();
    if (tid == 0) {
        float b = 0.0f;
#pragma unroll
        for (int i = 0; i < 8; ++i) b += s_red[i];
        atomicAdd(&g_acc, (double)b);
    }
}

__global__ void k_final(float* out) { out[0] = (float)g_acc; }

// ---------------- launch ----------------
extern "C" void kernel_launch(void* const* d_in, const int* in_sizes, int n_in,
                              void* d_out, int out_size) {
    const float* user_emb = (const float*)d_in[0];
    const float* item_emb = (const float*)d_in[1];
    const int*   mask     = (const int*)  d_in[2];
    const float* tq       = (const float*)d_in[3];
    const float* wgt      = (const float*)d_in[4];
    const int*   ridx     = (const int*)  d_in[5];

    k_zero<<<1, 256>>>();
    k_region_sum<<<(NU * 32) / 256, 256>>>(user_emb, ridx);
    k_region_loss<<<(NU * 32) / 256, 256>>>(user_emb, ridx);

    dim3 grid(NS / TSB, NU / TUB);
    k_main<<<grid, 256>>>(user_emb, item_emb, mask, tq, wgt);

    k_final<<<1, 1>>>((float*)d_out);
}